// round 12
// baseline (speedup 1.0000x reference)
#include <cuda_runtime.h>
#include <cuda_bf16.h>
#include <math.h>
#include <float.h>
#include <stdint.h>

// ---------------------------------------------------------------------------
// Problem constants
// ---------------------------------------------------------------------------
#define B        4
#define N        2048
#define DIM      512
#define HEADS    8
#define DHEAD    64
#define INNER    512
#define ROWS     (B*N)
#define NARROW_K 9
#define WIDE_K   9
#define WIDE_DIL 5

// ---------------------------------------------------------------------------
// Device scratch
// ---------------------------------------------------------------------------
__device__ __align__(16) float g_qkv[ROWS * 3 * INNER];
__device__ __align__(16) float g_qs [ROWS * INNER];
__device__ __align__(16) float g_ks [ROWS * INNER];
__device__ __align__(16) float g_vm [ROWS * INNER];
__device__ __align__(16) float g_ctx_part[B*HEADS*8*DHEAD*DHEAD];
__device__ __align__(16) float g_ctx[B*HEADS*DHEAD*DHEAD];
__device__ __align__(16) float g_attn[ROWS * INNER];
__device__ __align__(16) float g_tok [ROWS * DIM];
__device__ __align__(16) float g_xm  [ROWS * DIM];
__device__ __align__(16) float g_cn  [ROWS * DIM];
__device__ __align__(16) float g_cw  [ROWS * DIM];
__device__ __align__(16) float g_ln1 [ROWS * DIM];
__device__ __align__(16) float g_ff  [ROWS * DIM];
__device__ __align__(16) float g_wkn [NARROW_K*DIM*DIM];  // fp32 fallback conv w
__device__ __align__(16) float g_wkw [WIDE_K*DIM*DIM];
__device__ __align__(16) int   g_mask[ROWS];
__device__ int g_fb[5];   // fallback flags: qkv, op, convN, convW, ff

// bf16 split activations / weights for the MMA fast path
__device__ __align__(16) __nv_bfloat16 g_thi[ROWS*DIM],  g_tlo[ROWS*DIM];
__device__ __align__(16) __nv_bfloat16 g_ahi[ROWS*INNER],g_alo[ROWS*INNER];
__device__ __align__(16) __nv_bfloat16 g_xh [ROWS*DIM],  g_xl [ROWS*DIM];
__device__ __align__(16) __nv_bfloat16 g_l1h[ROWS*DIM],  g_l1l[ROWS*DIM];
__device__ __align__(16) __nv_bfloat16 g_wqh[3*INNER*DIM], g_wql[3*INNER*DIM];
__device__ __align__(16) __nv_bfloat16 g_woh[DIM*INNER],   g_wol[DIM*INNER];
__device__ __align__(16) __nv_bfloat16 g_wfh[DIM*DIM],     g_wfl[DIM*DIM];
__device__ __align__(16) __nv_bfloat16 g_wnh[NARROW_K*DIM*DIM], g_wnl[NARROW_K*DIM*DIM];
__device__ __align__(16) __nv_bfloat16 g_wwh[WIDE_K*DIM*DIM],   g_wwl[WIDE_K*DIM*DIM];

// ---------------------------------------------------------------------------
// Helpers
// ---------------------------------------------------------------------------
__device__ __forceinline__ float gelu_exact(float x) {
    return 0.5f * x * (1.0f + erff(x * 0.7071067811865476f));
}
__device__ __forceinline__ unsigned long long pack2(float x, float y) {
    unsigned long long r;
    asm("mov.b64 %0, {%1, %2};" : "=l"(r) : "f"(x), "f"(y));
    return r;
}
__device__ __forceinline__ void fma2(unsigned long long &d,
                                     unsigned long long a,
                                     unsigned long long b) {
    asm("fma.rn.f32x2 %0, %1, %2, %0;" : "+l"(d) : "l"(a), "l"(b));
}
__device__ __forceinline__ float2 unpack2(unsigned long long v) {
    float2 r;
    asm("mov.b64 {%0, %1}, %2;" : "=f"(r.x), "=f"(r.y) : "l"(v));
    return r;
}
__device__ __forceinline__ void bsplit(float x, __nv_bfloat16& h, __nv_bfloat16& l) {
    h = __float2bfloat16_rn(x);
    l = __float2bfloat16_rn(x - __bfloat162float(h));
}
#define MMA_BF16(d, a, b) \
    asm volatile("mma.sync.aligned.m16n8k16.row.col.f32.bf16.bf16.f32 " \
                 "{%0,%1,%2,%3}, {%4,%5,%6,%7}, {%8,%9}, {%0,%1,%2,%3};" \
                 : "+f"((d)[0]), "+f"((d)[1]), "+f"((d)[2]), "+f"((d)[3]) \
                 : "r"((a)[0]), "r"((a)[1]), "r"((a)[2]), "r"((a)[3]), \
                   "r"((b)[0]), "r"((b)[1]))

// ---------------------------------------------------------------------------
// Mask normalization + flag reset
// ---------------------------------------------------------------------------
__global__ void mask_prep_kernel(const unsigned char* raw) {
    __shared__ int is_bool;
    if (threadIdx.x == 0) {
        is_bool = 0;
        for (int f = 0; f < 5; f++) g_fb[f] = 0;
    }
    __syncthreads();
    for (int p = threadIdx.x; p < ROWS; p += blockDim.x)
        if ((p & 3) && raw[p]) is_bool = 1;
    __syncthreads();
    const int* as_int = (const int*)raw;
    for (int i = threadIdx.x; i < ROWS; i += blockDim.x)
        g_mask[i] = is_bool ? (raw[i] != 0) : (as_int[i] != 0);
}

// ---------------------------------------------------------------------------
// Splits / weight prep
// ---------------------------------------------------------------------------
__global__ void split_act_kernel(const float* __restrict__ src,
                                 __nv_bfloat16* __restrict__ h,
                                 __nv_bfloat16* __restrict__ l, int n) {
    int i = blockIdx.x * blockDim.x + threadIdx.x;
    if (i < n) { __nv_bfloat16 a, b; bsplit(src[i], a, b); h[i] = a; l[i] = b; }
}
__global__ void wsplit_dense_kernel(const float* __restrict__ w,
                                    __nv_bfloat16* __restrict__ oh,
                                    __nv_bfloat16* __restrict__ ol, int K, int Nc) {
    int i = blockIdx.x * blockDim.x + threadIdx.x;
    if (i >= K * Nc) return;
    int k = i / Nc, n = i - k * Nc;
    __nv_bfloat16 a, b; bsplit(w[i], a, b);
    oh[(size_t)n * K + k] = a; ol[(size_t)n * K + k] = b;
}
__global__ void wsplit_conv_kernel(const float* __restrict__ w,
                                   __nv_bfloat16* __restrict__ oh,
                                   __nv_bfloat16* __restrict__ ol) {
    int i = blockIdx.x * blockDim.x + threadIdx.x;
    if (i >= DIM * DIM * 9) return;
    int co = i / (DIM * 9);
    int r = i - co * (DIM * 9);
    int ci = r / 9, tap = r - ci * 9;
    __nv_bfloat16 a, b; bsplit(w[i], a, b);
    size_t o = ((size_t)tap * DIM + co) * DIM + ci;
    oh[o] = a; ol[o] = b;
}
// fp32 conv weight transpose for the fallback: w[co][ci][k] -> wk[k][ci][co]
__global__ void wtrans_kernel(const float* __restrict__ w, float* __restrict__ wk, int Kt) {
    int idx = blockIdx.x * blockDim.x + threadIdx.x;
    int total = DIM * DIM * Kt;
    if (idx >= total) return;
    int co = idx / (DIM * Kt);
    int r = idx - co * (DIM * Kt);
    int ci = r / Kt;
    int k = r - ci * Kt;
    wk[((size_t)k * DIM + ci) * DIM + co] = w[idx];
}

// ---------------------------------------------------------------------------
// Global-direct MMA engine — isomorphic to the PROVEN frag_test conventions.
// No shared memory. Each fragment register loaded straight from global at the
// exact (row,col) the PTX m16n8k16 spec dictates. Per-row OOB guards for taps.
// D[z,t,n] = sum_{tap,k} A[z, t+shift][k] * Bw[tap][n][k]; raw fp32 C out.
// ---------------------------------------------------------------------------
__global__ __launch_bounds__(256)
void mma_gemm_kernel(const __nv_bfloat16* __restrict__ Ahi,
                     const __nv_bfloat16* __restrict__ Alo,
                     const __nv_bfloat16* __restrict__ Bhi,
                     const __nv_bfloat16* __restrict__ Blo,
                     float* __restrict__ Cout,
                     int Ktot, int Ntot, int n_seq, int taps, int dil) {
    const int tid = threadIdx.x, wid = tid >> 5, lane = tid & 31;
    const int n0 = blockIdx.x * 128, t0 = blockIdx.y * 128, z = blockIdx.z;
    const int wrow = (wid >> 1) * 32;     // 0,32,64,96
    const int wcol = (wid & 1) * 64;      // 0,64
    const int grp = lane >> 2, qq = lane & 3;

    float acc[2][8][4];
#pragma unroll
    for (int mf = 0; mf < 2; mf++)
#pragma unroll
        for (int nf = 0; nf < 8; nf++)
#pragma unroll
            for (int q2 = 0; q2 < 4; q2++) acc[mf][nf][q2] = 0.f;

    const int ksteps = Ktot >> 4;
    for (int tap = 0; tap < taps; tap++) {
        const int shift = (tap - (taps >> 1)) * dil;
        const size_t bnbase = (size_t)tap * Ntot;
        for (int s = 0; s < ksteps; s++) {
            const int k0 = (s << 4) + 2 * qq;
            // A fragments: a0/a2 from row p1, a1/a3 from row p1+8 (PTX spec)
            uint32_t a_h[2][4], a_l[2][4];
#pragma unroll
            for (int mf = 0; mf < 2; mf++) {
                const int p1 = t0 + wrow + mf * 16 + grp + shift;
                const int p2 = p1 + 8;
                if ((unsigned)p1 < (unsigned)n_seq) {
                    const size_t o1 = ((size_t)z * n_seq + p1) * Ktot + k0;
                    a_h[mf][0] = *(const uint32_t*)(Ahi + o1);
                    a_h[mf][2] = *(const uint32_t*)(Ahi + o1 + 8);
                    a_l[mf][0] = *(const uint32_t*)(Alo + o1);
                    a_l[mf][2] = *(const uint32_t*)(Alo + o1 + 8);
                } else {
                    a_h[mf][0] = a_h[mf][2] = 0u;
                    a_l[mf][0] = a_l[mf][2] = 0u;
                }
                if ((unsigned)p2 < (unsigned)n_seq) {
                    const size_t o2 = ((size_t)z * n_seq + p2) * Ktot + k0;
                    a_h[mf][1] = *(const uint32_t*)(Ahi + o2);
                    a_h[mf][3] = *(const uint32_t*)(Ahi + o2 + 8);
                    a_l[mf][1] = *(const uint32_t*)(Alo + o2);
                    a_l[mf][3] = *(const uint32_t*)(Alo + o2 + 8);
                } else {
                    a_h[mf][1] = a_h[mf][3] = 0u;
                    a_l[mf][1] = a_l[mf][3] = 0u;
                }
            }
            // B fragments + MMAs
#pragma unroll
            for (int nf = 0; nf < 8; nf++) {
                const int nn = n0 + wcol + nf * 8 + grp;
                const size_t ob = (bnbase + nn) * Ktot + k0;
                uint32_t bh[2], bl[2];
                bh[0] = *(const uint32_t*)(Bhi + ob);
                bh[1] = *(const uint32_t*)(Bhi + ob + 8);
                bl[0] = *(const uint32_t*)(Blo + ob);
                bl[1] = *(const uint32_t*)(Blo + ob + 8);
#pragma unroll
                for (int mf = 0; mf < 2; mf++) {
                    MMA_BF16(acc[mf][nf], a_h[mf], bh);
                    MMA_BF16(acc[mf][nf], a_h[mf], bl);
                    MMA_BF16(acc[mf][nf], a_l[mf], bh);
                }
            }
        }
    }

    // epilogue: C fragment rows grp(+8), cols 2qq(+1) per PTX spec
#pragma unroll
    for (int mf = 0; mf < 2; mf++)
#pragma unroll
        for (int half = 0; half < 2; half++) {
            const int row = wrow + mf * 16 + grp + half * 8;
            const size_t grow = (size_t)z * n_seq + t0 + row;
#pragma unroll
            for (int nf = 0; nf < 8; nf++) {
                const int col = wcol + nf * 8 + 2 * qq;
                float v0 = acc[mf][nf][half * 2 + 0];
                float v1 = acc[mf][nf][half * 2 + 1];
                *(float2*)&Cout[grow * Ntot + col] = make_float2(v0, v1);
            }
        }
}

// ---------------------------------------------------------------------------
// Spot checkers: recompute sampled outputs from ORIGINAL fp32 tensors.
// ---------------------------------------------------------------------------
__global__ void check_gemm_kernel(const float* __restrict__ A,
                                  const float* __restrict__ Bw,
                                  const float* __restrict__ Cm,
                                  int K, int Nt, int* flag) {
    int i = blockIdx.x * blockDim.x + threadIdx.x;
    int row = (i * 53) & (ROWS - 1);
    int col = (int)(((long)i * 97) % Nt);
    float ref = 0.f;
    for (int k = 0; k < K; k++)
        ref += A[(size_t)row * K + k] * Bw[(size_t)k * Nt + col];
    float got = Cm[(size_t)row * Nt + col];
    if (fabsf(got - ref) > 5e-3f * fmaxf(1.0f, fabsf(ref))) atomicExch(flag, 1);
}
__global__ void check_conv_kernel(const float* __restrict__ w,  // [co][ci][9]
                                  const float* __restrict__ Cm,
                                  int dil, int* flag) {
    int i = blockIdx.x * blockDim.x + threadIdx.x;
    int gr = (i * 53) & (ROWS - 1);
    int co = (i * 97) & (DIM - 1);
    int t = gr & (N - 1);
    float ref = 0.f;
    for (int tap = 0; tap < 9; tap++) {
        int tt = t + (tap - 4) * dil;
        if ((unsigned)tt < (unsigned)N) {
            const float* xrow = g_xm + (size_t)(gr - t + tt) * DIM;
            const float* wr = w + (size_t)co * DIM * 9 + tap;
            for (int ci = 0; ci < DIM; ci++) ref += xrow[ci] * wr[ci * 9];
        }
    }
    float got = Cm[(size_t)gr * DIM + co];
    if (fabsf(got - ref) > 5e-3f * fmaxf(1.0f, fabsf(ref))) atomicExch(flag, 1);
}

// ---------------------------------------------------------------------------
// PROVEN fp32 fallback engines with device-flag early exit
// ---------------------------------------------------------------------------
__global__ void sgemm128_kernel(const int* __restrict__ flag,
                                const float* __restrict__ A,
                                const float* __restrict__ Bm,
                                float* __restrict__ C,
                                int M, int Nn, int K) {
    if (flag && *flag == 0) return;
    __shared__ float As[8][132];
    __shared__ float Bs[8][128];
    const int n0 = blockIdx.x * 128;
    const int m0 = blockIdx.y * 128;
    const int tid = threadIdx.x;
    const int tx = tid & 15, ty = tid >> 4;

    const int arow = tid >> 1;
    const int akq  = (tid & 1) * 4;
    const int bkk  = tid >> 5;
    const int bnq  = (tid & 31) * 4;

    const float* Aptr = A + (size_t)(m0 + arow) * K + akq;
    const float* Bptr = Bm + (size_t)bkk * Nn + n0 + bnq;

    float4 areg = *(const float4*)Aptr;
    float4 breg = *(const float4*)Bptr;

    unsigned long long acc[8][4];
#pragma unroll
    for (int i = 0; i < 8; i++)
#pragma unroll
        for (int j = 0; j < 4; j++) acc[i][j] = 0ull;

    const int nsteps = K >> 3;
    for (int s = 0; s < nsteps; s++) {
        As[akq + 0][arow] = areg.x;
        As[akq + 1][arow] = areg.y;
        As[akq + 2][arow] = areg.z;
        As[akq + 3][arow] = areg.w;
        *(float4*)&Bs[bkk][bnq] = breg;
        __syncthreads();
        if (s + 1 < nsteps) {
            areg = *(const float4*)(Aptr + (s + 1) * 8);
            breg = *(const float4*)(Bptr + (size_t)(s + 1) * 8 * Nn);
        }
#pragma unroll
        for (int kk = 0; kk < 8; kk++) {
            float4 a0 = *(float4*)&As[kk][ty * 4];
            float4 a1 = *(float4*)&As[kk][ty * 4 + 64];
            ulonglong2 b0 = *(ulonglong2*)&Bs[kk][tx * 4];
            ulonglong2 b1 = *(ulonglong2*)&Bs[kk][tx * 4 + 64];
            unsigned long long bb[4] = {b0.x, b0.y, b1.x, b1.y};
            unsigned long long av[8];
            av[0] = pack2(a0.x, a0.x); av[1] = pack2(a0.y, a0.y);
            av[2] = pack2(a0.z, a0.z); av[3] = pack2(a0.w, a0.w);
            av[4] = pack2(a1.x, a1.x); av[5] = pack2(a1.y, a1.y);
            av[6] = pack2(a1.z, a1.z); av[7] = pack2(a1.w, a1.w);
#pragma unroll
            for (int i = 0; i < 8; i++)
#pragma unroll
                for (int j = 0; j < 4; j++) fma2(acc[i][j], av[i], bb[j]);
        }
        __syncthreads();
    }

#pragma unroll
    for (int i = 0; i < 8; i++) {
        int row = m0 + ty * 4 + (i & 3) + ((i >= 4) ? 64 : 0);
#pragma unroll
        for (int half = 0; half < 2; half++) {
            int col = n0 + tx * 4 + half * 64;
            float2 v0 = unpack2(acc[i][half * 2 + 0]);
            float2 v1 = unpack2(acc[i][half * 2 + 1]);
            *(float4*)&C[(size_t)row * Nn + col] = make_float4(v0.x, v0.y, v1.x, v1.y);
        }
    }
}

__global__ void conv_gemm128_kernel(const int* __restrict__ flag,
                                    const float* __restrict__ wk,
                                    float* __restrict__ out, int dil) {
    if (*flag == 0) return;
    __shared__ float Xs[8][132];
    __shared__ float Ws[8][128];
    const int co0 = blockIdx.x * 128;
    const int t0 = blockIdx.y * 128;
    const int b = blockIdx.z;
    const int tid = threadIdx.x;
    const int tx = tid & 15, ty = tid >> 4;

    const int arow = tid >> 1;
    const int akq  = (tid & 1) * 4;
    const int bkk  = tid >> 5;
    const int bnq  = (tid & 31) * 4;

    unsigned long long acc[8][4];
#pragma unroll
    for (int i = 0; i < 8; i++)
#pragma unroll
        for (int j = 0; j < 4; j++) acc[i][j] = 0ull;

    const int total = 9 * 64;

    float4 areg, breg;
    {
        int shift = (0 - 4) * dil;
        int tt = t0 + arow + shift;
        areg = make_float4(0.f, 0.f, 0.f, 0.f);
        if (tt >= 0 && tt < N)
            areg = *(const float4*)&g_xm[(size_t)(b * N + tt) * DIM + akq];
        breg = *(const float4*)&wk[(size_t)bkk * DIM + co0 + bnq];
    }

    for (int s = 0; s < total; s++) {
        Xs[akq + 0][arow] = areg.x;
        Xs[akq + 1][arow] = areg.y;
        Xs[akq + 2][arow] = areg.z;
        Xs[akq + 3][arow] = areg.w;
        *(float4*)&Ws[bkk][bnq] = breg;
        __syncthreads();
        if (s + 1 < total) {
            int s2 = s + 1;
            int k2 = s2 >> 6;
            int ci2 = (s2 & 63) * 8;
            int shift = (k2 - 4) * dil;
            int tt = t0 + arow + shift;
            areg = make_float4(0.f, 0.f, 0.f, 0.f);
            if (tt >= 0 && tt < N)
                areg = *(const float4*)&g_xm[(size_t)(b * N + tt) * DIM + ci2 + akq];
            breg = *(const float4*)&wk[((size_t)k2 * DIM + ci2 + bkk) * DIM + co0 + bnq];
        }
#pragma unroll
        for (int kk = 0; kk < 8; kk++) {
            float4 a0 = *(float4*)&Xs[kk][ty * 4];
            float4 a1 = *(float4*)&Xs[kk][ty * 4 + 64];
            ulonglong2 b0 = *(ulonglong2*)&Ws[kk][tx * 4];
            ulonglong2 b1 = *(ulonglong2*)&Ws[kk][tx * 4 + 64];
            unsigned long long bb[4] = {b0.x, b0.y, b1.x, b1.y};
            unsigned long long av[8];
            av[0] = pack2(a0.x, a0.x); av[1] = pack2(a0.y, a0.y);
            av[2] = pack2(a0.z, a0.z); av[3] = pack2(a0.w, a0.w);
            av[4] = pack2(a1.x, a1.x); av[5] = pack2(a1.y, a1.y);
            av[6] = pack2(a1.z, a1.z); av[7] = pack2(a1.w, a1.w);
#pragma unroll
            for (int i = 0; i < 8; i++)
#pragma unroll
                for (int j = 0; j < 4; j++) fma2(acc[i][j], av[i], bb[j]);
        }
        __syncthreads();
    }

#pragma unroll
    for (int i = 0; i < 8; i++) {
        int t = t0 + ty * 4 + (i & 3) + ((i >= 4) ? 64 : 0);
#pragma unroll
        for (int half = 0; half < 2; half++) {
            int co = co0 + tx * 4 + half * 64;
            size_t idx = (size_t)(b * N + t) * DIM + co;
            float2 v0 = unpack2(acc[i][half * 2 + 0]);
            float2 v1 = unpack2(acc[i][half * 2 + 1]);
            *(float4*)&out[idx] = make_float4(v0.x, v0.y, v1.x, v1.y);
        }
    }
}

// ---------------------------------------------------------------------------
// attention small kernels (proven)
// ---------------------------------------------------------------------------
__global__ void q_v_kernel() {
    const int row = blockIdx.x;
    const int pos = row & (N - 1);
    const int tid = threadIdx.x;
    const int w = tid >> 5;
    const int l = tid & 31;

    float inv = expf(-(float)(2 * l) * (1.0f / 64.0f) * logf(10000.0f));
    float arg = (float)pos * inv;
    const float* qrow = g_qkv + (size_t)row * (3 * INNER);
    float x1 = qrow[w * 64 + l]      + sinf(arg);
    float x2 = qrow[w * 64 + l + 32] + cosf(arg);
    float m = fmaxf(x1, x2);
#pragma unroll
    for (int o = 16; o > 0; o >>= 1) m = fmaxf(m, __shfl_xor_sync(0xffffffffu, m, o));
    float e1 = expf(x1 - m), e2 = expf(x2 - m);
    float s = e1 + e2;
#pragma unroll
    for (int o = 16; o > 0; o >>= 1) s += __shfl_xor_sync(0xffffffffu, s, o);
    float r = 0.125f / s;
    g_qs[(size_t)row * INNER + w * 64 + l]      = e1 * r;
    g_qs[(size_t)row * INNER + w * 64 + l + 32] = e2 * r;

    float mk = g_mask[row] ? 1.0f : 0.0f;
    for (int i = tid; i < INNER; i += 256)
        g_vm[(size_t)row * INNER + i] = mk * qrow[2 * INNER + i];
}

__global__ void k_colsoftmax_kernel() {
    const int col = blockIdx.x;
    const int b = blockIdx.y;
    const int d = col & 63;
    const int tid = threadIdx.x;
    __shared__ float red[256];

    int i_ = (d < 32) ? d : (d - 32);
    float inv = expf(-(float)(2 * i_) * (1.0f / 64.0f) * logf(10000.0f));
    bool use_sin = (d < 32);

    float vals[8];
    float mx = -FLT_MAX;
#pragma unroll
    for (int j = 0; j < 8; j++) {
        int n = tid + 256 * j;
        int row = b * N + n;
        float arg = (float)n * inv;
        float rope = use_sin ? sinf(arg) : cosf(arg);
        float v = g_qkv[(size_t)row * (3 * INNER) + INNER + col] + rope;
        v = g_mask[row] ? v : -FLT_MAX;
        vals[j] = v;
        mx = fmaxf(mx, v);
    }
    red[tid] = mx; __syncthreads();
    for (int o = 128; o > 0; o >>= 1) {
        if (tid < o) red[tid] = fmaxf(red[tid], red[tid + o]);
        __syncthreads();
    }
    mx = red[0]; __syncthreads();

    float s = 0.f;
    float ev[8];
#pragma unroll
    for (int j = 0; j < 8; j++) {
        ev[j] = (vals[j] == -FLT_MAX) ? 0.f : expf(vals[j] - mx);
        s += ev[j];
    }
    red[tid] = s; __syncthreads();
    for (int o = 128; o > 0; o >>= 1) {
        if (tid < o) red[tid] += red[tid + o];
        __syncthreads();
    }
    float rs = 1.0f / red[0];
#pragma unroll
    for (int j = 0; j < 8; j++) {
        int n = tid + 256 * j;
        g_ks[(size_t)(b * N + n) * INNER + col] = ev[j] * rs;
    }
}

__global__ void ctx_partial_kernel() {
    const int bh = blockIdx.x;
    const int split = blockIdx.y;
    const int b = bh >> 3, h = bh & 7;
    const int tid = threadIdx.x;
    const int ty = tid >> 4, tx = tid & 15;
    __shared__ float Ks[16][64];
    __shared__ float Vs[16][64];

    float acc[4][4];
#pragma unroll
    for (int i = 0; i < 4; i++)
#pragma unroll
        for (int j = 0; j < 4; j++) acc[i][j] = 0.f;

    const int n0 = split * 256;
    for (int c = 0; c < 16; c++) {
        int nb = n0 + c * 16;
        int r = tid >> 6, colc = tid & 63;
#pragma unroll
        for (int i = 0; i < 4; i++) {
            int rr = r + 4 * i;
            size_t base = (size_t)(b * N + nb + rr) * INNER + h * 64 + colc;
            Ks[rr][colc] = g_ks[base];
            Vs[rr][colc] = g_vm[base];
        }
        __syncthreads();
#pragma unroll
        for (int kk = 0; kk < 16; kk++) {
            float a[4], bb[4];
#pragma unroll
            for (int i = 0; i < 4; i++) a[i] = Ks[kk][ty * 4 + i];
#pragma unroll
            for (int j = 0; j < 4; j++) bb[j] = Vs[kk][tx * 4 + j];
#pragma unroll
            for (int i = 0; i < 4; i++)
#pragma unroll
                for (int j = 0; j < 4; j++) acc[i][j] = fmaf(a[i], bb[j], acc[i][j]);
        }
        __syncthreads();
    }
    float* dst = g_ctx_part + (size_t)(bh * 8 + split) * 4096;
#pragma unroll
    for (int i = 0; i < 4; i++)
#pragma unroll
        for (int j = 0; j < 4; j++)
            dst[(ty * 4 + i) * 64 + tx * 4 + j] = acc[i][j];
}

__global__ void ctx_reduce_kernel() {
    int i = blockIdx.x * blockDim.x + threadIdx.x;
    if (i >= B * HEADS * 4096) return;
    int bh = i >> 12, pos = i & 4095;
    float s = 0.f;
#pragma unroll
    for (int sp = 0; sp < 8; sp++) s += g_ctx_part[(size_t)(bh * 8 + sp) * 4096 + pos];
    g_ctx[i] = s;
}

// apply context; write fp32 attn AND bf16 splits (fast path input)
__global__ void attn_apply_kernel() {
    const int blk = blockIdx.x;
    const int tile = blk & 63;
    const int h = (blk >> 6) & 7;
    const int b = blk >> 9;
    const int t0 = tile * 32;
    const int tid = threadIdx.x;
    __shared__ float ctx_sh[64 * 65];
    __shared__ float qs_sh[32 * 64];

    const float* ctxp = g_ctx + (size_t)(b * 8 + h) * 4096;
#pragma unroll
    for (int i = 0; i < 16; i++) {
        int idx = tid + 256 * i;
        ctx_sh[(idx >> 6) * 65 + (idx & 63)] = ctxp[idx];
    }
#pragma unroll
    for (int i = 0; i < 8; i++) {
        int idx = tid + 256 * i;
        int tok = idx >> 6, d = idx & 63;
        qs_sh[idx] = g_qs[(size_t)(b * N + t0 + tok) * INNER + h * 64 + d];
    }
    __syncthreads();
#pragma unroll
    for (int o = 0; o < 8; o++) {
        int idx = tid + 256 * o;
        int tok = idx >> 6, e = idx & 63;
        float s = 0.f;
#pragma unroll
        for (int d = 0; d < 64; d++)
            s = fmaf(qs_sh[tok * 64 + d], ctx_sh[d * 65 + e], s);
        size_t o2 = (size_t)(b * N + t0 + tok) * INNER + h * 64 + e;
        g_attn[o2] = s;
        __nv_bfloat16 hh, ll;
        bsplit(s, hh, ll);
        g_ahi[o2] = hh; g_alo[o2] = ll;
    }
}

// out-proj epilogue: tok += bias; xm = mask*tok (fp32) + bf16 splits
__global__ void op_epilogue_kernel(const float* __restrict__ b_out) {
    int i = blockIdx.x * blockDim.x + threadIdx.x;
    if (i >= ROWS * DIM) return;
    float t = g_tok[i] + b_out[i & (DIM - 1)];
    g_tok[i] = t;
    float xv = g_mask[i >> 9] ? t : 0.f;
    g_xm[i] = xv;
    __nv_bfloat16 h, l;
    bsplit(xv, h, l);
    g_xh[i] = h; g_xl[i] = l;
}

// ln1: v = tok + gelu(cn+bn) + gelu(cw+bw); LN -> g_ln1 fp32 + bf16 split
__global__ void ln1_fused_kernel(const float* __restrict__ bn,
                                 const float* __restrict__ bw,
                                 const float* __restrict__ g,
                                 const float* __restrict__ bvec) {
    const int row = blockIdx.x;
    const int tid = threadIdx.x;
    __shared__ float red[256];
    size_t base = (size_t)row * DIM;
    float v0 = g_tok[base + tid]
             + gelu_exact(g_cn[base + tid] + bn[tid])
             + gelu_exact(g_cw[base + tid] + bw[tid]);
    float v1 = g_tok[base + tid + 256]
             + gelu_exact(g_cn[base + tid + 256] + bn[tid + 256])
             + gelu_exact(g_cw[base + tid + 256] + bw[tid + 256]);
    red[tid] = v0 + v1; __syncthreads();
    for (int o = 128; o > 0; o >>= 1) {
        if (tid < o) red[tid] += red[tid + o];
        __syncthreads();
    }
    float mean = red[0] * (1.0f / DIM); __syncthreads();
    float d0 = v0 - mean, d1 = v1 - mean;
    red[tid] = d0 * d0 + d1 * d1; __syncthreads();
    for (int o = 128; o > 0; o >>= 1) {
        if (tid < o) red[tid] += red[tid + o];
        __syncthreads();
    }
    float var = red[0] * (1.0f / DIM);
    float rstd = rsqrtf(var + 1e-5f);
    float r0 = d0 * rstd * g[tid] + bvec[tid];
    float r1 = d1 * rstd * g[tid + 256] + bvec[tid + 256];
    g_ln1[base + tid] = r0;
    g_ln1[base + tid + 256] = r1;
    __nv_bfloat16 h, l;
    bsplit(r0, h, l); g_l1h[base + tid] = h;       g_l1l[base + tid] = l;
    bsplit(r1, h, l); g_l1h[base + tid + 256] = h; g_l1l[base + tid + 256] = l;
}

// ln2 over gelu(ff + ffb) -> output
__global__ void ln2_kernel(const float* __restrict__ ffb,
                           const float* __restrict__ g,
                           const float* __restrict__ bvec,
                           float* __restrict__ out) {
    const int row = blockIdx.x;
    const int tid = threadIdx.x;
    __shared__ float red[256];
    size_t base = (size_t)row * DIM;
    float v0 = gelu_exact(g_ff[base + tid] + ffb[tid]);
    float v1 = gelu_exact(g_ff[base + tid + 256] + ffb[tid + 256]);
    red[tid] = v0 + v1; __syncthreads();
    for (int o = 128; o > 0; o >>= 1) {
        if (tid < o) red[tid] += red[tid + o];
        __syncthreads();
    }
    float mean = red[0] * (1.0f / DIM); __syncthreads();
    float d0 = v0 - mean, d1 = v1 - mean;
    red[tid] = d0 * d0 + d1 * d1; __syncthreads();
    for (int o = 128; o > 0; o >>= 1) {
        if (tid < o) red[tid] += red[tid + o];
        __syncthreads();
    }
    float var = red[0] * (1.0f / DIM);
    float rstd = rsqrtf(var + 1e-5f);
    out[base + tid]       = d0 * rstd * g[tid] + bvec[tid];
    out[base + tid + 256] = d1 * rstd * g[tid + 256] + bvec[tid + 256];
}

// ---------------------------------------------------------------------------
// Launch
// ---------------------------------------------------------------------------
extern "C" void kernel_launch(void* const* d_in, const int* in_sizes, int n_in,
                              void* d_out, int out_size) {
    const float* tokens   = (const float*)d_in[0];
    const unsigned char* mask_raw = (const unsigned char*)d_in[1];
    const float* w_qkv    = (const float*)d_in[2];
    const float* w_out    = (const float*)d_in[3];
    const float* b_out    = (const float*)d_in[4];
    const float* w_narrow = (const float*)d_in[5];
    const float* b_narrow = (const float*)d_in[6];
    const float* w_wide   = (const float*)d_in[7];
    const float* b_wide   = (const float*)d_in[8];
    const float* ln1_g    = (const float*)d_in[9];
    const float* ln1_b    = (const float*)d_in[10];
    const float* ff_w     = (const float*)d_in[11];
    const float* ff_b     = (const float*)d_in[12];
    const float* ln2_g    = (const float*)d_in[13];
    const float* ln2_b    = (const float*)d_in[14];
    float* outp = (float*)d_out;

    float *p_qkv, *p_attn, *p_tok, *p_cn, *p_cw, *p_ln1, *p_ff, *p_wkn, *p_wkw;
    cudaGetSymbolAddress((void**)&p_qkv, g_qkv);
    cudaGetSymbolAddress((void**)&p_attn, g_attn);
    cudaGetSymbolAddress((void**)&p_tok, g_tok);
    cudaGetSymbolAddress((void**)&p_cn,  g_cn);
    cudaGetSymbolAddress((void**)&p_cw,  g_cw);
    cudaGetSymbolAddress((void**)&p_ln1, g_ln1);
    cudaGetSymbolAddress((void**)&p_ff,  g_ff);
    cudaGetSymbolAddress((void**)&p_wkn, g_wkn);
    cudaGetSymbolAddress((void**)&p_wkw, g_wkw);
    int* p_fb; cudaGetSymbolAddress((void**)&p_fb, g_fb);
#define BSYM(var, sym) __nv_bfloat16* var; cudaGetSymbolAddress((void**)&var, sym)
    BSYM(p_thi, g_thi); BSYM(p_tlo, g_tlo);
    BSYM(p_ahi, g_ahi); BSYM(p_alo, g_alo);
    BSYM(p_xh, g_xh);   BSYM(p_xl, g_xl);
    BSYM(p_l1h, g_l1h); BSYM(p_l1l, g_l1l);
    BSYM(p_wqh, g_wqh); BSYM(p_wql, g_wql);
    BSYM(p_woh, g_woh); BSYM(p_wol, g_wol);
    BSYM(p_wfh, g_wfh); BSYM(p_wfl, g_wfl);
    BSYM(p_wnh, g_wnh); BSYM(p_wnl, g_wnl);
    BSYM(p_wwh, g_wwh); BSYM(p_wwl, g_wwl);
#undef BSYM

    // 1. mask (+flag reset) + splits + weight prep (both paths)
    mask_prep_kernel<<<1, 256>>>(mask_raw);
    split_act_kernel<<<(ROWS*DIM + 255)/256, 256>>>(tokens, p_thi, p_tlo, ROWS*DIM);
    wsplit_dense_kernel<<<(DIM*3*INNER + 255)/256, 256>>>(w_qkv, p_wqh, p_wql, DIM, 3*INNER);
    wsplit_dense_kernel<<<(INNER*DIM + 255)/256, 256>>>(w_out, p_woh, p_wol, INNER, DIM);
    wsplit_dense_kernel<<<(DIM*DIM + 255)/256, 256>>>(ff_w, p_wfh, p_wfl, DIM, DIM);
    wsplit_conv_kernel<<<(DIM*DIM*9 + 255)/256, 256>>>(w_narrow, p_wnh, p_wnl);
    wsplit_conv_kernel<<<(DIM*DIM*9 + 255)/256, 256>>>(w_wide, p_wwh, p_wwl);
    wtrans_kernel<<<(DIM*DIM*9 + 255)/256, 256>>>(w_narrow, p_wkn, 9);
    wtrans_kernel<<<(DIM*DIM*9 + 255)/256, 256>>>(w_wide, p_wkw, 9);

    // 2. qkv: MMA fast path -> check -> fp32 fallback (early-exit)
    mma_gemm_kernel<<<dim3(3*INNER/128, ROWS/128, 1), 256>>>(
        p_thi, p_tlo, p_wqh, p_wql, p_qkv, DIM, 3*INNER, ROWS, 1, 0);
    check_gemm_kernel<<<4, 256>>>(tokens, w_qkv, p_qkv, DIM, 3*INNER, p_fb + 0);
    sgemm128_kernel<<<dim3(3*INNER/128, ROWS/128), 256>>>(
        p_fb + 0, tokens, w_qkv, p_qkv, ROWS, 3*INNER, DIM);

    // 3. attention small kernels
    q_v_kernel<<<ROWS, 256>>>();
    k_colsoftmax_kernel<<<dim3(INNER, B), 256>>>();
    ctx_partial_kernel<<<dim3(B*HEADS, 8), 256>>>();
    ctx_reduce_kernel<<<(B*HEADS*4096 + 255)/256, 256>>>();
    attn_apply_kernel<<<B*HEADS*(N/32), 256>>>();

    // 4. out-proj: MMA -> check -> fallback; epilogue (bias + masked split)
    mma_gemm_kernel<<<dim3(DIM/128, ROWS/128, 1), 256>>>(
        p_ahi, p_alo, p_woh, p_wol, p_tok, INNER, DIM, ROWS, 1, 0);
    check_gemm_kernel<<<4, 256>>>(p_attn, w_out, p_tok, INNER, DIM, p_fb + 1);
    sgemm128_kernel<<<dim3(DIM/128, ROWS/128), 256>>>(
        p_fb + 1, p_attn, w_out, p_tok, ROWS, DIM, INNER);
    op_epilogue_kernel<<<(ROWS*DIM + 255)/256, 256>>>(b_out);

    // 5. convs: MMA taps -> check -> fp32 fallback
    mma_gemm_kernel<<<dim3(DIM/128, N/128, B), 256>>>(
        p_xh, p_xl, p_wnh, p_wnl, p_cn, DIM, DIM, N, NARROW_K, 1);
    mma_gemm_kernel<<<dim3(DIM/128, N/128, B), 256>>>(
        p_xh, p_xl, p_wwh, p_wwl, p_cw, DIM, DIM, N, WIDE_K, WIDE_DIL);
    check_conv_kernel<<<2, 256>>>(w_narrow, p_cn, 1, p_fb + 2);
    check_conv_kernel<<<2, 256>>>(w_wide, p_cw, WIDE_DIL, p_fb + 3);
    conv_gemm128_kernel<<<dim3(DIM/128, N/128, B), 256>>>(p_fb + 2, p_wkn, p_cn, 1);
    conv_gemm128_kernel<<<dim3(DIM/128, N/128, B), 256>>>(p_fb + 3, p_wkw, p_cw, WIDE_DIL);

    // 6. ln1 (residual + gelu(conv+bias) fused) -> fp32 + bf16 split
    ln1_fused_kernel<<<ROWS, 256>>>(b_narrow, b_wide, ln1_g, ln1_b);

    // 7. ff: MMA -> check -> fallback
    mma_gemm_kernel<<<dim3(DIM/128, ROWS/128, 1), 256>>>(
        p_l1h, p_l1l, p_wfh, p_wfl, p_ff, DIM, DIM, ROWS, 1, 0);
    check_gemm_kernel<<<4, 256>>>(p_ln1, ff_w, p_ff, DIM, DIM, p_fb + 4);
    sgemm128_kernel<<<dim3(DIM/128, ROWS/128), 256>>>(
        p_fb + 4, p_ln1, ff_w, p_ff, ROWS, DIM, DIM);

    // 8. ln2 (gelu+bias fused) -> output
    ln2_kernel<<<ROWS, 256>>>(ff_b, ln2_g, ln2_b, outp);
}

// round 13
// speedup vs baseline: 2.9347x; 2.9347x over previous
#include <cuda_runtime.h>
#include <cuda_bf16.h>
#include <math.h>
#include <float.h>
#include <stdint.h>

// ---------------------------------------------------------------------------
// Problem constants
// ---------------------------------------------------------------------------
#define B        4
#define N        2048
#define DIM      512
#define HEADS    8
#define DHEAD    64
#define INNER    512
#define ROWS     (B*N)
#define NARROW_K 9
#define WIDE_K   9
#define WIDE_DIL 5

// ---------------------------------------------------------------------------
// Device scratch (fp32 only, ~233 MB)
// ---------------------------------------------------------------------------
__device__ __align__(16) float g_qkv[ROWS * 3 * INNER];
__device__ __align__(16) float g_qs [ROWS * INNER];
__device__ __align__(16) float g_ks [ROWS * INNER];
__device__ __align__(16) float g_vm [ROWS * INNER];
__device__ __align__(16) float g_ctx_part[B*HEADS*8*DHEAD*DHEAD];
__device__ __align__(16) float g_ctx[B*HEADS*DHEAD*DHEAD];
__device__ __align__(16) float g_attn[ROWS * INNER];
__device__ __align__(16) float g_tok [ROWS * DIM];
__device__ __align__(16) float g_xm  [ROWS * DIM];
__device__ __align__(16) float g_cn  [ROWS * DIM];   // narrow conv raw
__device__ __align__(16) float g_cw  [ROWS * DIM];   // wide conv raw
__device__ __align__(16) float g_ln1 [ROWS * DIM];
__device__ __align__(16) float g_ff  [ROWS * DIM];
__device__ __align__(16) float g_wkn [NARROW_K*DIM*DIM];  // [k][ci][co]
__device__ __align__(16) float g_wkw [WIDE_K*DIM*DIM];
__device__ __align__(16) int   g_mask[ROWS];

// ---------------------------------------------------------------------------
// Helpers
// ---------------------------------------------------------------------------
__device__ __forceinline__ float gelu_exact(float x) {
    return 0.5f * x * (1.0f + erff(x * 0.7071067811865476f));
}
__device__ __forceinline__ unsigned long long pack2(float x, float y) {
    unsigned long long r;
    asm("mov.b64 %0, {%1, %2};" : "=l"(r) : "f"(x), "f"(y));
    return r;
}
__device__ __forceinline__ void fma2(unsigned long long &d,
                                     unsigned long long a,
                                     unsigned long long b) {
    asm("fma.rn.f32x2 %0, %1, %2, %0;" : "+l"(d) : "l"(a), "l"(b));
}
__device__ __forceinline__ float2 unpack2(unsigned long long v) {
    float2 r;
    asm("mov.b64 {%0, %1}, %2;" : "=f"(r.x), "=f"(r.y) : "l"(v));
    return r;
}

// ---------------------------------------------------------------------------
// Mask normalization
// ---------------------------------------------------------------------------
__global__ void mask_prep_kernel(const unsigned char* raw) {
    __shared__ int is_bool;
    if (threadIdx.x == 0) is_bool = 0;
    __syncthreads();
    for (int p = threadIdx.x; p < ROWS; p += blockDim.x)
        if ((p & 3) && raw[p]) is_bool = 1;
    __syncthreads();
    const int* as_int = (const int*)raw;
    for (int i = threadIdx.x; i < ROWS; i += blockDim.x)
        g_mask[i] = is_bool ? (raw[i] != 0) : (as_int[i] != 0);
}

// ---------------------------------------------------------------------------
// 128x128 SGEMM, K-step 16, f32x2 FMA, register prefetch.
// Epilogue options: bias, gelu, masked secondary store (conv input).
// ---------------------------------------------------------------------------
__global__ __launch_bounds__(256, 2)
void sgemm16_kernel(const float* __restrict__ A,
                    const float* __restrict__ Bm,
                    const float* __restrict__ bias,
                    float* __restrict__ C,
                    float* __restrict__ C2masked,
                    int M, int Nn, int K, int do_gelu) {
    __shared__ float As[16][132];
    __shared__ float Bs[16][128];
    const int n0 = blockIdx.x * 128;
    const int m0 = blockIdx.y * 128;
    const int tid = threadIdx.x;
    const int tx = tid & 15, ty = tid >> 4;

    // A: float4 slot e -> arow=e>>2 (0..127), akq=(e&3)*4; e in {tid, tid+256}
    const int arow = tid >> 2;
    const int akq  = (tid & 3) * 4;
    // B: float4 slot e -> bkk=e>>5 (0..15), bnq=(e&31)*4
    const int bkk = tid >> 5;           // 0..7 ; +8 for second slot
    const int bnq = (tid & 31) * 4;

    const float* Aptr0 = A + (size_t)(m0 + arow) * K + akq;
    const float* Aptr1 = A + (size_t)(m0 + arow + 64) * K + akq;
    const float* Bptr0 = Bm + (size_t)bkk * Nn + n0 + bnq;
    const float* Bptr1 = Bm + (size_t)(bkk + 8) * Nn + n0 + bnq;

    float4 ar0 = *(const float4*)Aptr0;
    float4 ar1 = *(const float4*)Aptr1;
    float4 br0 = *(const float4*)Bptr0;
    float4 br1 = *(const float4*)Bptr1;

    unsigned long long acc[8][4];
#pragma unroll
    for (int i = 0; i < 8; i++)
#pragma unroll
        for (int j = 0; j < 4; j++) acc[i][j] = 0ull;

    const int nsteps = K >> 4;
    for (int s = 0; s < nsteps; s++) {
        As[akq + 0][arow] = ar0.x;  As[akq + 1][arow] = ar0.y;
        As[akq + 2][arow] = ar0.z;  As[akq + 3][arow] = ar0.w;
        As[akq + 0][arow + 64] = ar1.x;  As[akq + 1][arow + 64] = ar1.y;
        As[akq + 2][arow + 64] = ar1.z;  As[akq + 3][arow + 64] = ar1.w;
        *(float4*)&Bs[bkk][bnq] = br0;
        *(float4*)&Bs[bkk + 8][bnq] = br1;
        __syncthreads();
        if (s + 1 < nsteps) {
            ar0 = *(const float4*)(Aptr0 + (s + 1) * 16);
            ar1 = *(const float4*)(Aptr1 + (s + 1) * 16);
            br0 = *(const float4*)(Bptr0 + (size_t)(s + 1) * 16 * Nn);
            br1 = *(const float4*)(Bptr1 + (size_t)(s + 1) * 16 * Nn);
        }
#pragma unroll
        for (int kk = 0; kk < 16; kk++) {
            float4 a0 = *(float4*)&As[kk][ty * 4];
            float4 a1 = *(float4*)&As[kk][ty * 4 + 64];
            ulonglong2 b0 = *(ulonglong2*)&Bs[kk][tx * 4];
            ulonglong2 b1 = *(ulonglong2*)&Bs[kk][tx * 4 + 64];
            unsigned long long bb[4] = {b0.x, b0.y, b1.x, b1.y};
            unsigned long long av[8];
            av[0] = pack2(a0.x, a0.x); av[1] = pack2(a0.y, a0.y);
            av[2] = pack2(a0.z, a0.z); av[3] = pack2(a0.w, a0.w);
            av[4] = pack2(a1.x, a1.x); av[5] = pack2(a1.y, a1.y);
            av[6] = pack2(a1.z, a1.z); av[7] = pack2(a1.w, a1.w);
#pragma unroll
            for (int i = 0; i < 8; i++)
#pragma unroll
                for (int j = 0; j < 4; j++) fma2(acc[i][j], av[i], bb[j]);
        }
        __syncthreads();
    }

#pragma unroll
    for (int i = 0; i < 8; i++) {
        int row = m0 + ty * 4 + (i & 3) + ((i >= 4) ? 64 : 0);
        float mk = C2masked ? (g_mask[row] ? 1.0f : 0.0f) : 0.0f;
#pragma unroll
        for (int half = 0; half < 2; half++) {
            int col = n0 + tx * 4 + half * 64;
            float2 v0 = unpack2(acc[i][half * 2 + 0]);
            float2 v1 = unpack2(acc[i][half * 2 + 1]);
            float4 v = make_float4(v0.x, v0.y, v1.x, v1.y);
            if (bias) {
                v.x += bias[col]; v.y += bias[col + 1];
                v.z += bias[col + 2]; v.w += bias[col + 3];
            }
            if (do_gelu) {
                v.x = gelu_exact(v.x); v.y = gelu_exact(v.y);
                v.z = gelu_exact(v.z); v.w = gelu_exact(v.w);
            }
            *(float4*)&C[(size_t)row * Nn + col] = v;
            if (C2masked) {
                float4 vm = make_float4(v.x * mk, v.y * mk, v.z * mk, v.w * mk);
                *(float4*)&C2masked[(size_t)row * Nn + col] = vm;
            }
        }
    }
}

// ---------------------------------------------------------------------------
// q softmax (+rope, *0.125) and masked v
// ---------------------------------------------------------------------------
__global__ void q_v_kernel() {
    const int row = blockIdx.x;
    const int pos = row & (N - 1);
    const int tid = threadIdx.x;
    const int w = tid >> 5;
    const int l = tid & 31;

    float inv = expf(-(float)(2 * l) * (1.0f / 64.0f) * logf(10000.0f));
    float arg = (float)pos * inv;
    const float* qrow = g_qkv + (size_t)row * (3 * INNER);
    float x1 = qrow[w * 64 + l]      + sinf(arg);
    float x2 = qrow[w * 64 + l + 32] + cosf(arg);
    float m = fmaxf(x1, x2);
#pragma unroll
    for (int o = 16; o > 0; o >>= 1) m = fmaxf(m, __shfl_xor_sync(0xffffffffu, m, o));
    float e1 = expf(x1 - m), e2 = expf(x2 - m);
    float s = e1 + e2;
#pragma unroll
    for (int o = 16; o > 0; o >>= 1) s += __shfl_xor_sync(0xffffffffu, s, o);
    float r = 0.125f / s;
    g_qs[(size_t)row * INNER + w * 64 + l]      = e1 * r;
    g_qs[(size_t)row * INNER + w * 64 + l + 32] = e2 * r;

    float mk = g_mask[row] ? 1.0f : 0.0f;
    for (int i = tid; i < INNER; i += 256)
        g_vm[(size_t)row * INNER + i] = mk * qrow[2 * INNER + i];
}

// ---------------------------------------------------------------------------
// k column softmax over sequence axis
// ---------------------------------------------------------------------------
__global__ void k_colsoftmax_kernel() {
    const int col = blockIdx.x;
    const int b = blockIdx.y;
    const int d = col & 63;
    const int tid = threadIdx.x;
    __shared__ float red[256];

    int i_ = (d < 32) ? d : (d - 32);
    float inv = expf(-(float)(2 * i_) * (1.0f / 64.0f) * logf(10000.0f));
    bool use_sin = (d < 32);

    float vals[8];
    float mx = -FLT_MAX;
#pragma unroll
    for (int j = 0; j < 8; j++) {
        int n = tid + 256 * j;
        int row = b * N + n;
        float arg = (float)n * inv;
        float rope = use_sin ? sinf(arg) : cosf(arg);
        float v = g_qkv[(size_t)row * (3 * INNER) + INNER + col] + rope;
        v = g_mask[row] ? v : -FLT_MAX;
        vals[j] = v;
        mx = fmaxf(mx, v);
    }
    red[tid] = mx; __syncthreads();
    for (int o = 128; o > 0; o >>= 1) {
        if (tid < o) red[tid] = fmaxf(red[tid], red[tid + o]);
        __syncthreads();
    }
    mx = red[0]; __syncthreads();

    float s = 0.f;
    float ev[8];
#pragma unroll
    for (int j = 0; j < 8; j++) {
        ev[j] = (vals[j] == -FLT_MAX) ? 0.f : expf(vals[j] - mx);
        s += ev[j];
    }
    red[tid] = s; __syncthreads();
    for (int o = 128; o > 0; o >>= 1) {
        if (tid < o) red[tid] += red[tid + o];
        __syncthreads();
    }
    float rs = 1.0f / red[0];
#pragma unroll
    for (int j = 0; j < 8; j++) {
        int n = tid + 256 * j;
        g_ks[(size_t)(b * N + n) * INNER + col] = ev[j] * rs;
    }
}

// ---------------------------------------------------------------------------
// context partial + reduce
// ---------------------------------------------------------------------------
__global__ void ctx_partial_kernel() {
    const int bh = blockIdx.x;
    const int split = blockIdx.y;
    const int b = bh >> 3, h = bh & 7;
    const int tid = threadIdx.x;
    const int ty = tid >> 4, tx = tid & 15;
    __shared__ float Ks[16][64];
    __shared__ float Vs[16][64];

    float acc[4][4];
#pragma unroll
    for (int i = 0; i < 4; i++)
#pragma unroll
        for (int j = 0; j < 4; j++) acc[i][j] = 0.f;

    const int n0 = split * 256;
    for (int c = 0; c < 16; c++) {
        int nb = n0 + c * 16;
        int r = tid >> 6, colc = tid & 63;
#pragma unroll
        for (int i = 0; i < 4; i++) {
            int rr = r + 4 * i;
            size_t base = (size_t)(b * N + nb + rr) * INNER + h * 64 + colc;
            Ks[rr][colc] = g_ks[base];
            Vs[rr][colc] = g_vm[base];
        }
        __syncthreads();
#pragma unroll
        for (int kk = 0; kk < 16; kk++) {
            float a[4], bb[4];
#pragma unroll
            for (int i = 0; i < 4; i++) a[i] = Ks[kk][ty * 4 + i];
#pragma unroll
            for (int j = 0; j < 4; j++) bb[j] = Vs[kk][tx * 4 + j];
#pragma unroll
            for (int i = 0; i < 4; i++)
#pragma unroll
                for (int j = 0; j < 4; j++) acc[i][j] = fmaf(a[i], bb[j], acc[i][j]);
        }
        __syncthreads();
    }
    float* dst = g_ctx_part + (size_t)(bh * 8 + split) * 4096;
#pragma unroll
    for (int i = 0; i < 4; i++)
#pragma unroll
        for (int j = 0; j < 4; j++)
            dst[(ty * 4 + i) * 64 + tx * 4 + j] = acc[i][j];
}

__global__ void ctx_reduce_kernel() {
    int i = blockIdx.x * blockDim.x + threadIdx.x;
    if (i >= B * HEADS * 4096) return;
    int bh = i >> 12, pos = i & 4095;
    float s = 0.f;
#pragma unroll
    for (int sp = 0; sp < 8; sp++) s += g_ctx_part[(size_t)(bh * 8 + sp) * 4096 + pos];
    g_ctx[i] = s;
}

// ---------------------------------------------------------------------------
// apply context to q
// ---------------------------------------------------------------------------
__global__ void attn_apply_kernel() {
    const int blk = blockIdx.x;
    const int tile = blk & 63;
    const int h = (blk >> 6) & 7;
    const int b = blk >> 9;
    const int t0 = tile * 32;
    const int tid = threadIdx.x;
    __shared__ float ctx_sh[64 * 65];
    __shared__ float qs_sh[32 * 64];

    const float* ctxp = g_ctx + (size_t)(b * 8 + h) * 4096;
#pragma unroll
    for (int i = 0; i < 16; i++) {
        int idx = tid + 256 * i;
        ctx_sh[(idx >> 6) * 65 + (idx & 63)] = ctxp[idx];
    }
#pragma unroll
    for (int i = 0; i < 8; i++) {
        int idx = tid + 256 * i;
        int tok = idx >> 6, d = idx & 63;
        qs_sh[idx] = g_qs[(size_t)(b * N + t0 + tok) * INNER + h * 64 + d];
    }
    __syncthreads();
#pragma unroll
    for (int o = 0; o < 8; o++) {
        int idx = tid + 256 * o;
        int tok = idx >> 6, e = idx & 63;
        float s = 0.f;
#pragma unroll
        for (int d = 0; d < 64; d++)
            s = fmaf(qs_sh[tok * 64 + d], ctx_sh[d * 65 + e], s);
        g_attn[(size_t)(b * N + t0 + tok) * INNER + h * 64 + e] = s;
    }
}

// ---------------------------------------------------------------------------
// conv weight transpose: w[co][ci][k] -> wk[k][ci][co]
// ---------------------------------------------------------------------------
__global__ void wtrans_kernel(const float* __restrict__ w, float* __restrict__ wk, int Kt) {
    int idx = blockIdx.x * blockDim.x + threadIdx.x;
    int total = DIM * DIM * Kt;
    if (idx >= total) return;
    int co = idx / (DIM * Kt);
    int r = idx - co * (DIM * Kt);
    int ci = r / Kt;
    int k = r - ci * Kt;
    wk[((size_t)k * DIM + ci) * DIM + co] = w[idx];
}

// ---------------------------------------------------------------------------
// implicit-GEMM dilated conv1d, 128x128 tile, K-step 16, raw fp32 output
// grid: (co_tiles=4, t_tiles=16, b=4), block 256
// ---------------------------------------------------------------------------
__global__ __launch_bounds__(256, 2)
void conv16_kernel(const float* __restrict__ wk,
                   float* __restrict__ out, int dil) {
    __shared__ float Xs[16][132];
    __shared__ float Ws[16][128];
    const int co0 = blockIdx.x * 128;
    const int t0 = blockIdx.y * 128;
    const int b = blockIdx.z;
    const int tid = threadIdx.x;
    const int tx = tid & 15, ty = tid >> 4;

    const int arow = tid >> 2;
    const int akq  = (tid & 3) * 4;
    const int bkk = tid >> 5;           // 0..7 ; +8 second slot
    const int bnq = (tid & 31) * 4;

    unsigned long long acc[8][4];
#pragma unroll
    for (int i = 0; i < 8; i++)
#pragma unroll
        for (int j = 0; j < 4; j++) acc[i][j] = 0ull;

    const int total = 9 * 32;   // taps * (512/16)

    float4 ar0, ar1, br0, br1;
    // prologue: s = 0 -> tap 0, ci0 = 0
    {
        const int shift = (0 - 4) * dil;
        int tt0 = t0 + arow + shift;
        int tt1 = tt0 + 64;
        ar0 = make_float4(0.f, 0.f, 0.f, 0.f);
        ar1 = ar0;
        if (tt0 >= 0 && tt0 < N)
            ar0 = *(const float4*)&g_xm[(size_t)(b * N + tt0) * DIM + akq];
        if (tt1 >= 0 && tt1 < N)
            ar1 = *(const float4*)&g_xm[(size_t)(b * N + tt1) * DIM + akq];
        br0 = *(const float4*)&wk[(size_t)bkk * DIM + co0 + bnq];
        br1 = *(const float4*)&wk[(size_t)(bkk + 8) * DIM + co0 + bnq];
    }

    for (int s = 0; s < total; s++) {
        Xs[akq + 0][arow] = ar0.x;  Xs[akq + 1][arow] = ar0.y;
        Xs[akq + 2][arow] = ar0.z;  Xs[akq + 3][arow] = ar0.w;
        Xs[akq + 0][arow + 64] = ar1.x;  Xs[akq + 1][arow + 64] = ar1.y;
        Xs[akq + 2][arow + 64] = ar1.z;  Xs[akq + 3][arow + 64] = ar1.w;
        *(float4*)&Ws[bkk][bnq] = br0;
        *(float4*)&Ws[bkk + 8][bnq] = br1;
        __syncthreads();
        if (s + 1 < total) {
            const int s2 = s + 1;
            const int k2 = s2 >> 5;
            const int ci2 = (s2 & 31) * 16;
            const int shift = (k2 - 4) * dil;
            int tt0 = t0 + arow + shift;
            int tt1 = tt0 + 64;
            ar0 = make_float4(0.f, 0.f, 0.f, 0.f);
            ar1 = ar0;
            if (tt0 >= 0 && tt0 < N)
                ar0 = *(const float4*)&g_xm[(size_t)(b * N + tt0) * DIM + ci2 + akq];
            if (tt1 >= 0 && tt1 < N)
                ar1 = *(const float4*)&g_xm[(size_t)(b * N + tt1) * DIM + ci2 + akq];
            br0 = *(const float4*)&wk[((size_t)k2 * DIM + ci2 + bkk) * DIM + co0 + bnq];
            br1 = *(const float4*)&wk[((size_t)k2 * DIM + ci2 + bkk + 8) * DIM + co0 + bnq];
        }
#pragma unroll
        for (int kk = 0; kk < 16; kk++) {
            float4 a0 = *(float4*)&Xs[kk][ty * 4];
            float4 a1 = *(float4*)&Xs[kk][ty * 4 + 64];
            ulonglong2 b0 = *(ulonglong2*)&Ws[kk][tx * 4];
            ulonglong2 b1 = *(ulonglong2*)&Ws[kk][tx * 4 + 64];
            unsigned long long bb[4] = {b0.x, b0.y, b1.x, b1.y};
            unsigned long long av[8];
            av[0] = pack2(a0.x, a0.x); av[1] = pack2(a0.y, a0.y);
            av[2] = pack2(a0.z, a0.z); av[3] = pack2(a0.w, a0.w);
            av[4] = pack2(a1.x, a1.x); av[5] = pack2(a1.y, a1.y);
            av[6] = pack2(a1.z, a1.z); av[7] = pack2(a1.w, a1.w);
#pragma unroll
            for (int i = 0; i < 8; i++)
#pragma unroll
                for (int j = 0; j < 4; j++) fma2(acc[i][j], av[i], bb[j]);
        }
        __syncthreads();
    }

#pragma unroll
    for (int i = 0; i < 8; i++) {
        int t = t0 + ty * 4 + (i & 3) + ((i >= 4) ? 64 : 0);
#pragma unroll
        for (int half = 0; half < 2; half++) {
            int co = co0 + tx * 4 + half * 64;
            size_t idx = (size_t)(b * N + t) * DIM + co;
            float2 v0 = unpack2(acc[i][half * 2 + 0]);
            float2 v1 = unpack2(acc[i][half * 2 + 1]);
            *(float4*)&out[idx] = make_float4(v0.x, v0.y, v1.x, v1.y);
        }
    }
}

// ---------------------------------------------------------------------------
// ln1: v = tok + gelu(cn + bn) + gelu(cw + bw); LN -> g_ln1
// ---------------------------------------------------------------------------
__global__ void ln1_fused_kernel(const float* __restrict__ bn,
                                 const float* __restrict__ bw,
                                 const float* __restrict__ g,
                                 const float* __restrict__ bvec) {
    const int row = blockIdx.x;
    const int tid = threadIdx.x;
    __shared__ float red[256];
    size_t base = (size_t)row * DIM;
    float v0 = g_tok[base + tid]
             + gelu_exact(g_cn[base + tid] + bn[tid])
             + gelu_exact(g_cw[base + tid] + bw[tid]);
    float v1 = g_tok[base + tid + 256]
             + gelu_exact(g_cn[base + tid + 256] + bn[tid + 256])
             + gelu_exact(g_cw[base + tid + 256] + bw[tid + 256]);
    red[tid] = v0 + v1; __syncthreads();
    for (int o = 128; o > 0; o >>= 1) {
        if (tid < o) red[tid] += red[tid + o];
        __syncthreads();
    }
    float mean = red[0] * (1.0f / DIM); __syncthreads();
    float d0 = v0 - mean, d1 = v1 - mean;
    red[tid] = d0 * d0 + d1 * d1; __syncthreads();
    for (int o = 128; o > 0; o >>= 1) {
        if (tid < o) red[tid] += red[tid + o];
        __syncthreads();
    }
    float var = red[0] * (1.0f / DIM);
    float rstd = rsqrtf(var + 1e-5f);
    g_ln1[base + tid]       = d0 * rstd * g[tid] + bvec[tid];
    g_ln1[base + tid + 256] = d1 * rstd * g[tid + 256] + bvec[tid + 256];
}

// ---------------------------------------------------------------------------
// ln2 (plain) -> output
// ---------------------------------------------------------------------------
__global__ void ln2_kernel(const float* __restrict__ x,
                           const float* __restrict__ g,
                           const float* __restrict__ bvec,
                           float* __restrict__ out) {
    const int row = blockIdx.x;
    const int tid = threadIdx.x;
    __shared__ float red[256];
    float v0 = x[(size_t)row * DIM + tid];
    float v1 = x[(size_t)row * DIM + tid + 256];
    red[tid] = v0 + v1; __syncthreads();
    for (int o = 128; o > 0; o >>= 1) {
        if (tid < o) red[tid] += red[tid + o];
        __syncthreads();
    }
    float mean = red[0] * (1.0f / DIM); __syncthreads();
    float d0 = v0 - mean, d1 = v1 - mean;
    red[tid] = d0 * d0 + d1 * d1; __syncthreads();
    for (int o = 128; o > 0; o >>= 1) {
        if (tid < o) red[tid] += red[tid + o];
        __syncthreads();
    }
    float var = red[0] * (1.0f / DIM);
    float rstd = rsqrtf(var + 1e-5f);
    out[(size_t)row * DIM + tid]       = d0 * rstd * g[tid] + bvec[tid];
    out[(size_t)row * DIM + tid + 256] = d1 * rstd * g[tid + 256] + bvec[tid + 256];
}

// ---------------------------------------------------------------------------
// Launch
// ---------------------------------------------------------------------------
extern "C" void kernel_launch(void* const* d_in, const int* in_sizes, int n_in,
                              void* d_out, int out_size) {
    const float* tokens   = (const float*)d_in[0];
    const unsigned char* mask_raw = (const unsigned char*)d_in[1];
    const float* w_qkv    = (const float*)d_in[2];
    const float* w_out    = (const float*)d_in[3];
    const float* b_out    = (const float*)d_in[4];
    const float* w_narrow = (const float*)d_in[5];
    const float* b_narrow = (const float*)d_in[6];
    const float* w_wide   = (const float*)d_in[7];
    const float* b_wide   = (const float*)d_in[8];
    const float* ln1_g    = (const float*)d_in[9];
    const float* ln1_b    = (const float*)d_in[10];
    const float* ff_w     = (const float*)d_in[11];
    const float* ff_b     = (const float*)d_in[12];
    const float* ln2_g    = (const float*)d_in[13];
    const float* ln2_b    = (const float*)d_in[14];
    float* outp = (float*)d_out;

    float *p_qkv, *p_attn, *p_tok, *p_xm, *p_cn, *p_cw, *p_ln1, *p_ff, *p_wkn, *p_wkw;
    cudaGetSymbolAddress((void**)&p_qkv, g_qkv);
    cudaGetSymbolAddress((void**)&p_attn, g_attn);
    cudaGetSymbolAddress((void**)&p_tok, g_tok);
    cudaGetSymbolAddress((void**)&p_xm,  g_xm);
    cudaGetSymbolAddress((void**)&p_cn,  g_cn);
    cudaGetSymbolAddress((void**)&p_cw,  g_cw);
    cudaGetSymbolAddress((void**)&p_ln1, g_ln1);
    cudaGetSymbolAddress((void**)&p_ff,  g_ff);
    cudaGetSymbolAddress((void**)&p_wkn, g_wkn);
    cudaGetSymbolAddress((void**)&p_wkw, g_wkw);

    // 1. mask
    mask_prep_kernel<<<1, 256>>>(mask_raw);

    // 2. qkv GEMM (8192 x 1536 x 512)
    sgemm16_kernel<<<dim3(3 * INNER / 128, ROWS / 128), 256>>>(
        tokens, w_qkv, nullptr, p_qkv, nullptr, ROWS, 3 * INNER, DIM, 0);

    // 3. attention small kernels
    q_v_kernel<<<ROWS, 256>>>();
    k_colsoftmax_kernel<<<dim3(INNER, B), 256>>>();
    ctx_partial_kernel<<<dim3(B * HEADS, 8), 256>>>();
    ctx_reduce_kernel<<<(B * HEADS * 4096 + 255) / 256, 256>>>();
    attn_apply_kernel<<<B * HEADS * (N / 32), 256>>>();

    // 4. out projection (+bias) with fused masked store for conv input
    sgemm16_kernel<<<dim3(DIM / 128, ROWS / 128), 256>>>(
        p_attn, w_out, b_out, p_tok, p_xm, ROWS, DIM, INNER, 0);

    // 5. conv weight transposes
    wtrans_kernel<<<(DIM * DIM * NARROW_K + 255) / 256, 256>>>(w_narrow, p_wkn, NARROW_K);
    wtrans_kernel<<<(DIM * DIM * WIDE_K + 255) / 256, 256>>>(w_wide, p_wkw, WIDE_K);

    // 6. convs (implicit GEMM, raw outputs; bias+gelu+residual fused into ln1)
    conv16_kernel<<<dim3(DIM / 128, N / 128, B), 256>>>(p_wkn, p_cn, 1);
    conv16_kernel<<<dim3(DIM / 128, N / 128, B), 256>>>(p_wkw, p_cw, WIDE_DIL);

    // 7. ln1 (residual + gelu(conv+bias) fused)
    ln1_fused_kernel<<<ROWS, 256>>>(b_narrow, b_wide, ln1_g, ln1_b);

    // 8. ff GEMM + bias + gelu
    sgemm16_kernel<<<dim3(DIM / 128, ROWS / 128), 256>>>(
        p_ln1, ff_w, ff_b, p_ff, nullptr, ROWS, DIM, DIM, 1);

    // 9. ln2 -> output
    ln2_kernel<<<ROWS, 256>>>(p_ff, ln2_g, ln2_b, outp);
}

// round 14
// speedup vs baseline: 3.0378x; 1.0351x over previous
#include <cuda_runtime.h>
#include <cuda_bf16.h>
#include <math.h>
#include <float.h>
#include <stdint.h>

// ---------------------------------------------------------------------------
// Problem constants
// ---------------------------------------------------------------------------
#define B        4
#define N        2048
#define DIM      512
#define HEADS    8
#define DHEAD    64
#define INNER    512
#define ROWS     (B*N)
#define NARROW_K 9
#define WIDE_K   9
#define WIDE_DIL 5

// ---------------------------------------------------------------------------
// Device scratch (fp32 only)
// ---------------------------------------------------------------------------
__device__ __align__(16) float g_qkv[ROWS * 3 * INNER];
__device__ __align__(16) float g_qs [ROWS * INNER];
__device__ __align__(16) float g_ks [ROWS * INNER];
__device__ __align__(16) float g_vm [ROWS * INNER];
__device__ __align__(16) float g_ctx_part[B*HEADS*8*DHEAD*DHEAD];
__device__ __align__(16) float g_ctx[B*HEADS*DHEAD*DHEAD];
__device__ __align__(16) float g_attn[ROWS * INNER];
__device__ __align__(16) float g_tok [ROWS * DIM];
__device__ __align__(16) float g_xm  [ROWS * DIM];
__device__ __align__(16) float g_cn  [ROWS * DIM];   // narrow conv raw
__device__ __align__(16) float g_cw  [ROWS * DIM];   // wide conv raw
__device__ __align__(16) float g_ln1 [ROWS * DIM];
__device__ __align__(16) float g_ff  [ROWS * DIM];
__device__ __align__(16) float g_wkn [NARROW_K*DIM*DIM];  // [k][ci][co]
__device__ __align__(16) float g_wkw [WIDE_K*DIM*DIM];
__device__ __align__(16) int   g_mask[ROWS];

// ---------------------------------------------------------------------------
// Helpers
// ---------------------------------------------------------------------------
__device__ __forceinline__ float gelu_exact(float x) {
    return 0.5f * x * (1.0f + erff(x * 0.7071067811865476f));
}
__device__ __forceinline__ unsigned long long pack2(float x, float y) {
    unsigned long long r;
    asm("mov.b64 %0, {%1, %2};" : "=l"(r) : "f"(x), "f"(y));
    return r;
}
__device__ __forceinline__ void fma2(unsigned long long &d,
                                     unsigned long long a,
                                     unsigned long long b) {
    asm("fma.rn.f32x2 %0, %1, %2, %0;" : "+l"(d) : "l"(a), "l"(b));
}
__device__ __forceinline__ float2 unpack2(unsigned long long v) {
    float2 r;
    asm("mov.b64 {%0, %1}, %2;" : "=f"(r.x), "=f"(r.y) : "l"(v));
    return r;
}

// ---------------------------------------------------------------------------
// Mask normalization
// ---------------------------------------------------------------------------
__global__ void mask_prep_kernel(const unsigned char* raw) {
    __shared__ int is_bool;
    if (threadIdx.x == 0) is_bool = 0;
    __syncthreads();
    for (int p = threadIdx.x; p < ROWS; p += blockDim.x)
        if ((p & 3) && raw[p]) is_bool = 1;
    __syncthreads();
    const int* as_int = (const int*)raw;
    for (int i = threadIdx.x; i < ROWS; i += blockDim.x)
        g_mask[i] = is_bool ? (raw[i] != 0) : (as_int[i] != 0);
}

// ---------------------------------------------------------------------------
// 128x128 SGEMM, K-step 16, f32x2 FMA, register prefetch.
// Epilogue options: bias, gelu, masked secondary store (conv input).
// ---------------------------------------------------------------------------
__global__ __launch_bounds__(256, 2)
void sgemm16_kernel(const float* __restrict__ A,
                    const float* __restrict__ Bm,
                    const float* __restrict__ bias,
                    float* __restrict__ C,
                    float* __restrict__ C2masked,
                    int M, int Nn, int K, int do_gelu) {
    __shared__ float As[16][132];
    __shared__ float Bs[16][128];
    const int n0 = blockIdx.x * 128;
    const int m0 = blockIdx.y * 128;
    const int tid = threadIdx.x;
    const int tx = tid & 15, ty = tid >> 4;

    const int arow = tid >> 2;
    const int akq  = (tid & 3) * 4;
    const int bkk = tid >> 5;
    const int bnq = (tid & 31) * 4;

    const float* Aptr0 = A + (size_t)(m0 + arow) * K + akq;
    const float* Aptr1 = A + (size_t)(m0 + arow + 64) * K + akq;
    const float* Bptr0 = Bm + (size_t)bkk * Nn + n0 + bnq;
    const float* Bptr1 = Bm + (size_t)(bkk + 8) * Nn + n0 + bnq;

    float4 ar0 = *(const float4*)Aptr0;
    float4 ar1 = *(const float4*)Aptr1;
    float4 br0 = *(const float4*)Bptr0;
    float4 br1 = *(const float4*)Bptr1;

    unsigned long long acc[8][4];
#pragma unroll
    for (int i = 0; i < 8; i++)
#pragma unroll
        for (int j = 0; j < 4; j++) acc[i][j] = 0ull;

    const int nsteps = K >> 4;
    for (int s = 0; s < nsteps; s++) {
        As[akq + 0][arow] = ar0.x;  As[akq + 1][arow] = ar0.y;
        As[akq + 2][arow] = ar0.z;  As[akq + 3][arow] = ar0.w;
        As[akq + 0][arow + 64] = ar1.x;  As[akq + 1][arow + 64] = ar1.y;
        As[akq + 2][arow + 64] = ar1.z;  As[akq + 3][arow + 64] = ar1.w;
        *(float4*)&Bs[bkk][bnq] = br0;
        *(float4*)&Bs[bkk + 8][bnq] = br1;
        __syncthreads();
        if (s + 1 < nsteps) {
            ar0 = *(const float4*)(Aptr0 + (s + 1) * 16);
            ar1 = *(const float4*)(Aptr1 + (s + 1) * 16);
            br0 = *(const float4*)(Bptr0 + (size_t)(s + 1) * 16 * Nn);
            br1 = *(const float4*)(Bptr1 + (size_t)(s + 1) * 16 * Nn);
        }
#pragma unroll
        for (int kk = 0; kk < 16; kk++) {
            float4 a0 = *(float4*)&As[kk][ty * 4];
            float4 a1 = *(float4*)&As[kk][ty * 4 + 64];
            ulonglong2 b0 = *(ulonglong2*)&Bs[kk][tx * 4];
            ulonglong2 b1 = *(ulonglong2*)&Bs[kk][tx * 4 + 64];
            unsigned long long bb[4] = {b0.x, b0.y, b1.x, b1.y};
            unsigned long long av[8];
            av[0] = pack2(a0.x, a0.x); av[1] = pack2(a0.y, a0.y);
            av[2] = pack2(a0.z, a0.z); av[3] = pack2(a0.w, a0.w);
            av[4] = pack2(a1.x, a1.x); av[5] = pack2(a1.y, a1.y);
            av[6] = pack2(a1.z, a1.z); av[7] = pack2(a1.w, a1.w);
#pragma unroll
            for (int i = 0; i < 8; i++)
#pragma unroll
                for (int j = 0; j < 4; j++) fma2(acc[i][j], av[i], bb[j]);
        }
        __syncthreads();
    }

#pragma unroll
    for (int i = 0; i < 8; i++) {
        int row = m0 + ty * 4 + (i & 3) + ((i >= 4) ? 64 : 0);
        float mk = C2masked ? (g_mask[row] ? 1.0f : 0.0f) : 0.0f;
#pragma unroll
        for (int half = 0; half < 2; half++) {
            int col = n0 + tx * 4 + half * 64;
            float2 v0 = unpack2(acc[i][half * 2 + 0]);
            float2 v1 = unpack2(acc[i][half * 2 + 1]);
            float4 v = make_float4(v0.x, v0.y, v1.x, v1.y);
            if (bias) {
                v.x += bias[col]; v.y += bias[col + 1];
                v.z += bias[col + 2]; v.w += bias[col + 3];
            }
            if (do_gelu) {
                v.x = gelu_exact(v.x); v.y = gelu_exact(v.y);
                v.z = gelu_exact(v.z); v.w = gelu_exact(v.w);
            }
            *(float4*)&C[(size_t)row * Nn + col] = v;
            if (C2masked) {
                float4 vm = make_float4(v.x * mk, v.y * mk, v.z * mk, v.w * mk);
                *(float4*)&C2masked[(size_t)row * Nn + col] = vm;
            }
        }
    }
}

// ---------------------------------------------------------------------------
// q softmax (+rope, *0.125) and masked v
// ---------------------------------------------------------------------------
__global__ void q_v_kernel() {
    const int row = blockIdx.x;
    const int pos = row & (N - 1);
    const int tid = threadIdx.x;
    const int w = tid >> 5;
    const int l = tid & 31;

    float inv = expf(-(float)(2 * l) * (1.0f / 64.0f) * logf(10000.0f));
    float arg = (float)pos * inv;
    const float* qrow = g_qkv + (size_t)row * (3 * INNER);
    float x1 = qrow[w * 64 + l]      + sinf(arg);
    float x2 = qrow[w * 64 + l + 32] + cosf(arg);
    float m = fmaxf(x1, x2);
#pragma unroll
    for (int o = 16; o > 0; o >>= 1) m = fmaxf(m, __shfl_xor_sync(0xffffffffu, m, o));
    float e1 = expf(x1 - m), e2 = expf(x2 - m);
    float s = e1 + e2;
#pragma unroll
    for (int o = 16; o > 0; o >>= 1) s += __shfl_xor_sync(0xffffffffu, s, o);
    float r = 0.125f / s;
    g_qs[(size_t)row * INNER + w * 64 + l]      = e1 * r;
    g_qs[(size_t)row * INNER + w * 64 + l + 32] = e2 * r;

    float mk = g_mask[row] ? 1.0f : 0.0f;
    for (int i = tid; i < INNER; i += 256)
        g_vm[(size_t)row * INNER + i] = mk * qrow[2 * INNER + i];
}

// ---------------------------------------------------------------------------
// k column softmax over sequence axis
// ---------------------------------------------------------------------------
__global__ void k_colsoftmax_kernel() {
    const int col = blockIdx.x;
    const int b = blockIdx.y;
    const int d = col & 63;
    const int tid = threadIdx.x;
    __shared__ float red[256];

    int i_ = (d < 32) ? d : (d - 32);
    float inv = expf(-(float)(2 * i_) * (1.0f / 64.0f) * logf(10000.0f));
    bool use_sin = (d < 32);

    float vals[8];
    float mx = -FLT_MAX;
#pragma unroll
    for (int j = 0; j < 8; j++) {
        int n = tid + 256 * j;
        int row = b * N + n;
        float arg = (float)n * inv;
        float rope = use_sin ? sinf(arg) : cosf(arg);
        float v = g_qkv[(size_t)row * (3 * INNER) + INNER + col] + rope;
        v = g_mask[row] ? v : -FLT_MAX;
        vals[j] = v;
        mx = fmaxf(mx, v);
    }
    red[tid] = mx; __syncthreads();
    for (int o = 128; o > 0; o >>= 1) {
        if (tid < o) red[tid] = fmaxf(red[tid], red[tid + o]);
        __syncthreads();
    }
    mx = red[0]; __syncthreads();

    float s = 0.f;
    float ev[8];
#pragma unroll
    for (int j = 0; j < 8; j++) {
        ev[j] = (vals[j] == -FLT_MAX) ? 0.f : expf(vals[j] - mx);
        s += ev[j];
    }
    red[tid] = s; __syncthreads();
    for (int o = 128; o > 0; o >>= 1) {
        if (tid < o) red[tid] += red[tid + o];
        __syncthreads();
    }
    float rs = 1.0f / red[0];
#pragma unroll
    for (int j = 0; j < 8; j++) {
        int n = tid + 256 * j;
        g_ks[(size_t)(b * N + n) * INNER + col] = ev[j] * rs;
    }
}

// ---------------------------------------------------------------------------
// context partial + reduce
// ---------------------------------------------------------------------------
__global__ void ctx_partial_kernel() {
    const int bh = blockIdx.x;
    const int split = blockIdx.y;
    const int b = bh >> 3, h = bh & 7;
    const int tid = threadIdx.x;
    const int ty = tid >> 4, tx = tid & 15;
    __shared__ float Ks[16][64];
    __shared__ float Vs[16][64];

    float acc[4][4];
#pragma unroll
    for (int i = 0; i < 4; i++)
#pragma unroll
        for (int j = 0; j < 4; j++) acc[i][j] = 0.f;

    const int n0 = split * 256;
    for (int c = 0; c < 16; c++) {
        int nb = n0 + c * 16;
        int r = tid >> 6, colc = tid & 63;
#pragma unroll
        for (int i = 0; i < 4; i++) {
            int rr = r + 4 * i;
            size_t base = (size_t)(b * N + nb + rr) * INNER + h * 64 + colc;
            Ks[rr][colc] = g_ks[base];
            Vs[rr][colc] = g_vm[base];
        }
        __syncthreads();
#pragma unroll
        for (int kk = 0; kk < 16; kk++) {
            float a[4], bb[4];
#pragma unroll
            for (int i = 0; i < 4; i++) a[i] = Ks[kk][ty * 4 + i];
#pragma unroll
            for (int j = 0; j < 4; j++) bb[j] = Vs[kk][tx * 4 + j];
#pragma unroll
            for (int i = 0; i < 4; i++)
#pragma unroll
                for (int j = 0; j < 4; j++) acc[i][j] = fmaf(a[i], bb[j], acc[i][j]);
        }
        __syncthreads();
    }
    float* dst = g_ctx_part + (size_t)(bh * 8 + split) * 4096;
#pragma unroll
    for (int i = 0; i < 4; i++)
#pragma unroll
        for (int j = 0; j < 4; j++)
            dst[(ty * 4 + i) * 64 + tx * 4 + j] = acc[i][j];
}

__global__ void ctx_reduce_kernel() {
    int i = blockIdx.x * blockDim.x + threadIdx.x;
    if (i >= B * HEADS * 4096) return;
    int bh = i >> 12, pos = i & 4095;
    float s = 0.f;
#pragma unroll
    for (int sp = 0; sp < 8; sp++) s += g_ctx_part[(size_t)(bh * 8 + sp) * 4096 + pos];
    g_ctx[i] = s;
}

// ---------------------------------------------------------------------------
// apply context to q
// ---------------------------------------------------------------------------
__global__ void attn_apply_kernel() {
    const int blk = blockIdx.x;
    const int tile = blk & 63;
    const int h = (blk >> 6) & 7;
    const int b = blk >> 9;
    const int t0 = tile * 32;
    const int tid = threadIdx.x;
    __shared__ float ctx_sh[64 * 65];
    __shared__ float qs_sh[32 * 64];

    const float* ctxp = g_ctx + (size_t)(b * 8 + h) * 4096;
#pragma unroll
    for (int i = 0; i < 16; i++) {
        int idx = tid + 256 * i;
        ctx_sh[(idx >> 6) * 65 + (idx & 63)] = ctxp[idx];
    }
#pragma unroll
    for (int i = 0; i < 8; i++) {
        int idx = tid + 256 * i;
        int tok = idx >> 6, d = idx & 63;
        qs_sh[idx] = g_qs[(size_t)(b * N + t0 + tok) * INNER + h * 64 + d];
    }
    __syncthreads();
#pragma unroll
    for (int o = 0; o < 8; o++) {
        int idx = tid + 256 * o;
        int tok = idx >> 6, e = idx & 63;
        float s = 0.f;
#pragma unroll
        for (int d = 0; d < 64; d++)
            s = fmaf(qs_sh[tok * 64 + d], ctx_sh[d * 65 + e], s);
        g_attn[(size_t)(b * N + t0 + tok) * INNER + h * 64 + e] = s;
    }
}

// ---------------------------------------------------------------------------
// conv weight transpose: w[co][ci][k] -> wk[k][ci][co]
// ---------------------------------------------------------------------------
__global__ void wtrans_kernel(const float* __restrict__ w, float* __restrict__ wk, int Kt) {
    int idx = blockIdx.x * blockDim.x + threadIdx.x;
    int total = DIM * DIM * Kt;
    if (idx >= total) return;
    int co = idx / (DIM * Kt);
    int r = idx - co * (DIM * Kt);
    int ci = r / Kt;
    int k = r - ci * Kt;
    wk[((size_t)k * DIM + ci) * DIM + co] = w[idx];
}

// ---------------------------------------------------------------------------
// MERGED implicit-GEMM conv1d: both convs in ONE launch for wave packing.
// grid: (co_tiles=4, t_tiles=16, 8) — z = b + 4*which.
// Body identical to proven R13 conv16; only parameter selection added.
// ---------------------------------------------------------------------------
__global__ __launch_bounds__(256, 2)
void conv_merged_kernel(const float* __restrict__ wkn,
                        const float* __restrict__ wkw,
                        float* __restrict__ outn,
                        float* __restrict__ outw) {
    const int zz = blockIdx.z;
    const int b = zz & 3;
    const int which = zz >> 2;
    const float* __restrict__ wk = which ? wkw : wkn;
    float* __restrict__ out = which ? outw : outn;
    const int dil = which ? WIDE_DIL : 1;

    __shared__ float Xs[16][132];
    __shared__ float Ws[16][128];
    const int co0 = blockIdx.x * 128;
    const int t0 = blockIdx.y * 128;
    const int tid = threadIdx.x;
    const int tx = tid & 15, ty = tid >> 4;

    const int arow = tid >> 2;
    const int akq  = (tid & 3) * 4;
    const int bkk = tid >> 5;
    const int bnq = (tid & 31) * 4;

    unsigned long long acc[8][4];
#pragma unroll
    for (int i = 0; i < 8; i++)
#pragma unroll
        for (int j = 0; j < 4; j++) acc[i][j] = 0ull;

    const int total = 9 * 32;

    float4 ar0, ar1, br0, br1;
    {
        const int shift = (0 - 4) * dil;
        int tt0 = t0 + arow + shift;
        int tt1 = tt0 + 64;
        ar0 = make_float4(0.f, 0.f, 0.f, 0.f);
        ar1 = ar0;
        if (tt0 >= 0 && tt0 < N)
            ar0 = *(const float4*)&g_xm[(size_t)(b * N + tt0) * DIM + akq];
        if (tt1 >= 0 && tt1 < N)
            ar1 = *(const float4*)&g_xm[(size_t)(b * N + tt1) * DIM + akq];
        br0 = *(const float4*)&wk[(size_t)bkk * DIM + co0 + bnq];
        br1 = *(const float4*)&wk[(size_t)(bkk + 8) * DIM + co0 + bnq];
    }

    for (int s = 0; s < total; s++) {
        Xs[akq + 0][arow] = ar0.x;  Xs[akq + 1][arow] = ar0.y;
        Xs[akq + 2][arow] = ar0.z;  Xs[akq + 3][arow] = ar0.w;
        Xs[akq + 0][arow + 64] = ar1.x;  Xs[akq + 1][arow + 64] = ar1.y;
        Xs[akq + 2][arow + 64] = ar1.z;  Xs[akq + 3][arow + 64] = ar1.w;
        *(float4*)&Ws[bkk][bnq] = br0;
        *(float4*)&Ws[bkk + 8][bnq] = br1;
        __syncthreads();
        if (s + 1 < total) {
            const int s2 = s + 1;
            const int k2 = s2 >> 5;
            const int ci2 = (s2 & 31) * 16;
            const int shift = (k2 - 4) * dil;
            int tt0 = t0 + arow + shift;
            int tt1 = tt0 + 64;
            ar0 = make_float4(0.f, 0.f, 0.f, 0.f);
            ar1 = ar0;
            if (tt0 >= 0 && tt0 < N)
                ar0 = *(const float4*)&g_xm[(size_t)(b * N + tt0) * DIM + ci2 + akq];
            if (tt1 >= 0 && tt1 < N)
                ar1 = *(const float4*)&g_xm[(size_t)(b * N + tt1) * DIM + ci2 + akq];
            br0 = *(const float4*)&wk[((size_t)k2 * DIM + ci2 + bkk) * DIM + co0 + bnq];
            br1 = *(const float4*)&wk[((size_t)k2 * DIM + ci2 + bkk + 8) * DIM + co0 + bnq];
        }
#pragma unroll
        for (int kk = 0; kk < 16; kk++) {
            float4 a0 = *(float4*)&Xs[kk][ty * 4];
            float4 a1 = *(float4*)&Xs[kk][ty * 4 + 64];
            ulonglong2 b0 = *(ulonglong2*)&Ws[kk][tx * 4];
            ulonglong2 b1 = *(ulonglong2*)&Ws[kk][tx * 4 + 64];
            unsigned long long bb[4] = {b0.x, b0.y, b1.x, b1.y};
            unsigned long long av[8];
            av[0] = pack2(a0.x, a0.x); av[1] = pack2(a0.y, a0.y);
            av[2] = pack2(a0.z, a0.z); av[3] = pack2(a0.w, a0.w);
            av[4] = pack2(a1.x, a1.x); av[5] = pack2(a1.y, a1.y);
            av[6] = pack2(a1.z, a1.z); av[7] = pack2(a1.w, a1.w);
#pragma unroll
            for (int i = 0; i < 8; i++)
#pragma unroll
                for (int j = 0; j < 4; j++) fma2(acc[i][j], av[i], bb[j]);
        }
        __syncthreads();
    }

#pragma unroll
    for (int i = 0; i < 8; i++) {
        int t = t0 + ty * 4 + (i & 3) + ((i >= 4) ? 64 : 0);
#pragma unroll
        for (int half = 0; half < 2; half++) {
            int co = co0 + tx * 4 + half * 64;
            size_t idx = (size_t)(b * N + t) * DIM + co;
            float2 v0 = unpack2(acc[i][half * 2 + 0]);
            float2 v1 = unpack2(acc[i][half * 2 + 1]);
            *(float4*)&out[idx] = make_float4(v0.x, v0.y, v1.x, v1.y);
        }
    }
}

// ---------------------------------------------------------------------------
// ln1: v = tok + gelu(cn + bn) + gelu(cw + bw); LN -> g_ln1
// ---------------------------------------------------------------------------
__global__ void ln1_fused_kernel(const float* __restrict__ bn,
                                 const float* __restrict__ bw,
                                 const float* __restrict__ g,
                                 const float* __restrict__ bvec) {
    const int row = blockIdx.x;
    const int tid = threadIdx.x;
    __shared__ float red[256];
    size_t base = (size_t)row * DIM;
    float v0 = g_tok[base + tid]
             + gelu_exact(g_cn[base + tid] + bn[tid])
             + gelu_exact(g_cw[base + tid] + bw[tid]);
    float v1 = g_tok[base + tid + 256]
             + gelu_exact(g_cn[base + tid + 256] + bn[tid + 256])
             + gelu_exact(g_cw[base + tid + 256] + bw[tid + 256]);
    red[tid] = v0 + v1; __syncthreads();
    for (int o = 128; o > 0; o >>= 1) {
        if (tid < o) red[tid] += red[tid + o];
        __syncthreads();
    }
    float mean = red[0] * (1.0f / DIM); __syncthreads();
    float d0 = v0 - mean, d1 = v1 - mean;
    red[tid] = d0 * d0 + d1 * d1; __syncthreads();
    for (int o = 128; o > 0; o >>= 1) {
        if (tid < o) red[tid] += red[tid + o];
        __syncthreads();
    }
    float var = red[0] * (1.0f / DIM);
    float rstd = rsqrtf(var + 1e-5f);
    g_ln1[base + tid]       = d0 * rstd * g[tid] + bvec[tid];
    g_ln1[base + tid + 256] = d1 * rstd * g[tid + 256] + bvec[tid + 256];
}

// ---------------------------------------------------------------------------
// ln2 (plain) -> output
// ---------------------------------------------------------------------------
__global__ void ln2_kernel(const float* __restrict__ x,
                           const float* __restrict__ g,
                           const float* __restrict__ bvec,
                           float* __restrict__ out) {
    const int row = blockIdx.x;
    const int tid = threadIdx.x;
    __shared__ float red[256];
    float v0 = x[(size_t)row * DIM + tid];
    float v1 = x[(size_t)row * DIM + tid + 256];
    red[tid] = v0 + v1; __syncthreads();
    for (int o = 128; o > 0; o >>= 1) {
        if (tid < o) red[tid] += red[tid + o];
        __syncthreads();
    }
    float mean = red[0] * (1.0f / DIM); __syncthreads();
    float d0 = v0 - mean, d1 = v1 - mean;
    red[tid] = d0 * d0 + d1 * d1; __syncthreads();
    for (int o = 128; o > 0; o >>= 1) {
        if (tid < o) red[tid] += red[tid + o];
        __syncthreads();
    }
    float var = red[0] * (1.0f / DIM);
    float rstd = rsqrtf(var + 1e-5f);
    out[(size_t)row * DIM + tid]       = d0 * rstd * g[tid] + bvec[tid];
    out[(size_t)row * DIM + tid + 256] = d1 * rstd * g[tid + 256] + bvec[tid + 256];
}

// ---------------------------------------------------------------------------
// Launch
// ---------------------------------------------------------------------------
extern "C" void kernel_launch(void* const* d_in, const int* in_sizes, int n_in,
                              void* d_out, int out_size) {
    const float* tokens   = (const float*)d_in[0];
    const unsigned char* mask_raw = (const unsigned char*)d_in[1];
    const float* w_qkv    = (const float*)d_in[2];
    const float* w_out    = (const float*)d_in[3];
    const float* b_out    = (const float*)d_in[4];
    const float* w_narrow = (const float*)d_in[5];
    const float* b_narrow = (const float*)d_in[6];
    const float* w_wide   = (const float*)d_in[7];
    const float* b_wide   = (const float*)d_in[8];
    const float* ln1_g    = (const float*)d_in[9];
    const float* ln1_b    = (const float*)d_in[10];
    const float* ff_w     = (const float*)d_in[11];
    const float* ff_b     = (const float*)d_in[12];
    const float* ln2_g    = (const float*)d_in[13];
    const float* ln2_b    = (const float*)d_in[14];
    float* outp = (float*)d_out;

    float *p_qkv, *p_attn, *p_tok, *p_xm, *p_cn, *p_cw, *p_ln1, *p_ff, *p_wkn, *p_wkw;
    cudaGetSymbolAddress((void**)&p_qkv, g_qkv);
    cudaGetSymbolAddress((void**)&p_attn, g_attn);
    cudaGetSymbolAddress((void**)&p_tok, g_tok);
    cudaGetSymbolAddress((void**)&p_xm,  g_xm);
    cudaGetSymbolAddress((void**)&p_cn,  g_cn);
    cudaGetSymbolAddress((void**)&p_cw,  g_cw);
    cudaGetSymbolAddress((void**)&p_ln1, g_ln1);
    cudaGetSymbolAddress((void**)&p_ff,  g_ff);
    cudaGetSymbolAddress((void**)&p_wkn, g_wkn);
    cudaGetSymbolAddress((void**)&p_wkw, g_wkw);

    // 1. mask
    mask_prep_kernel<<<1, 256>>>(mask_raw);

    // 2. qkv GEMM (8192 x 1536 x 512)
    sgemm16_kernel<<<dim3(3 * INNER / 128, ROWS / 128), 256>>>(
        tokens, w_qkv, nullptr, p_qkv, nullptr, ROWS, 3 * INNER, DIM, 0);

    // 3. attention small kernels
    q_v_kernel<<<ROWS, 256>>>();
    k_colsoftmax_kernel<<<dim3(INNER, B), 256>>>();
    ctx_partial_kernel<<<dim3(B * HEADS, 8), 256>>>();
    ctx_reduce_kernel<<<(B * HEADS * 4096 + 255) / 256, 256>>>();
    attn_apply_kernel<<<B * HEADS * (N / 32), 256>>>();

    // 4. out projection (+bias) with fused masked store for conv input
    sgemm16_kernel<<<dim3(DIM / 128, ROWS / 128), 256>>>(
        p_attn, w_out, b_out, p_tok, p_xm, ROWS, DIM, INNER, 0);

    // 5. conv weight transposes
    wtrans_kernel<<<(DIM * DIM * NARROW_K + 255) / 256, 256>>>(w_narrow, p_wkn, NARROW_K);
    wtrans_kernel<<<(DIM * DIM * WIDE_K + 255) / 256, 256>>>(w_wide, p_wkw, WIDE_K);

    // 6. BOTH convs in one launch (512 blocks — wave packing)
    conv_merged_kernel<<<dim3(DIM / 128, N / 128, 2 * B), 256>>>(
        p_wkn, p_wkw, p_cn, p_cw);

    // 7. ln1 (residual + gelu(conv+bias) fused)
    ln1_fused_kernel<<<ROWS, 256>>>(b_narrow, b_wide, ln1_g, ln1_b);

    // 8. ff GEMM + bias + gelu
    sgemm16_kernel<<<dim3(DIM / 128, ROWS / 128), 256>>>(
        p_ln1, ff_w, ff_b, p_ff, nullptr, ROWS, DIM, DIM, 1);

    // 9. ln2 -> output
    ln2_kernel<<<ROWS, 256>>>(p_ff, ln2_g, ln2_b, outp);
}